// round 1
// baseline (speedup 1.0000x reference)
#include <cuda_runtime.h>
#include <math.h>
#include <float.h>
#include <stdint.h>

// Problem constants
#define Dm    1024
#define Pfull 131072
#define Bm    4096
#define Hh    4
#define HDm   256
#define TOPK  16
#define CHUNK 64
#define NC    (Pfull / CHUNK)   // 2048 compressed prototypes
#define ALPHA_SCORES 2.5f       // 1 / (H * TEMP) = 1 / 0.4

// ---------------- scratch (static device globals; no allocation) -------------
__device__ float g_protos[NC * Dm];     // 8 MB  compressed+normalized prototypes
__device__ float g_qr[Bm * Dm];         // 16 MB query router proj (normalized in place)
__device__ float g_kr[NC * Dm];         // 8 MB  key router proj (normalized in place)
__device__ float g_scores[Bm * NC];     // 32 MB routing scores
__device__ float g_topw[Bm * TOPK];
__device__ int   g_topi[Bm * TOPK];
__device__ float g_retr[Bm * Dm];       // 16 MB blended retrieval

// ---------------- 1) chunk compression + L2 norm -----------------------------
// one block per chunk; 256 threads; thread t owns cols [4t, 4t+4)
__global__ void compress_kernel(const float* __restrict__ protos,
                                const int* __restrict__ ev)
{
    const int c   = blockIdx.x;
    const int tid = threadIdx.x;
    __shared__ float w[CHUNK];
    __shared__ float red[256];

    if (tid < CHUNK) w[tid] = (float)ev[c * CHUNK + tid] + 1e-8f;
    __syncthreads();
    if (tid == 0) {
        float s = 0.f;
        #pragma unroll
        for (int r = 0; r < CHUNK; r++) s += w[r];
        red[0] = 1.0f / s;
    }
    __syncthreads();
    const float invs = red[0];
    if (tid < CHUNK) w[tid] *= invs;
    __syncthreads();

    float4 acc = make_float4(0.f, 0.f, 0.f, 0.f);
    const float4* base = (const float4*)(protos + (size_t)c * CHUNK * Dm);
    #pragma unroll 4
    for (int r = 0; r < CHUNK; r++) {
        const float wr = w[r];
        float4 p = base[r * (Dm / 4) + tid];
        acc.x += wr * p.x; acc.y += wr * p.y;
        acc.z += wr * p.z; acc.w += wr * p.w;
    }
    red[tid] = acc.x * acc.x + acc.y * acc.y + acc.z * acc.z + acc.w * acc.w;
    __syncthreads();
    for (int s = 128; s > 0; s >>= 1) {
        if (tid < s) red[tid] += red[tid + s];
        __syncthreads();
    }
    const float inv = 1.0f / fmaxf(sqrtf(red[0]), 1e-12f);
    acc.x *= inv; acc.y *= inv; acc.z *= inv; acc.w *= inv;
    ((float4*)(g_protos + (size_t)c * Dm))[tid] = acc;
}

// ---------------- 2) NT SGEMM: C[M,N] = alpha * A[M,K] @ B[N,K]^T ------------
// 128x128x8 tile, 256 threads, 8x8 per thread, packed fma.rn.f32x2 accumulators
__global__ __launch_bounds__(256, 2)
void sgemm_nt(const float* __restrict__ A, const float* __restrict__ Bmat,
              float* __restrict__ C, int M, int N, int K, float alpha)
{
    const int BM = 128, BN = 128, BK = 8;
    __shared__ float As[BK][BM];
    __shared__ float Bs[BK][BN];

    const int tid  = threadIdx.x;
    const int lrow = tid >> 1;          // 0..127
    const int lkv  = (tid & 1) << 2;    // 0 or 4
    const float* Ab = A    + (size_t)(blockIdx.y * BM + lrow) * K + lkv;
    const float* Bb = Bmat + (size_t)(blockIdx.x * BN + lrow) * K + lkv;

    const int tx = tid & 15;            // 0..15 -> N micro-tile
    const int ty = tid >> 4;            // 0..15 -> M micro-tile

    unsigned long long acc[8][4];       // 8 rows x 4 col-pairs (f32x2)
    #pragma unroll
    for (int i = 0; i < 8; i++)
        #pragma unroll
        for (int j = 0; j < 4; j++) acc[i][j] = 0ull;

    for (int k0 = 0; k0 < K; k0 += BK) {
        float4 a4 = *(const float4*)(Ab + k0);
        float4 b4 = *(const float4*)(Bb + k0);
        As[lkv + 0][lrow] = a4.x; As[lkv + 1][lrow] = a4.y;
        As[lkv + 2][lrow] = a4.z; As[lkv + 3][lrow] = a4.w;
        Bs[lkv + 0][lrow] = b4.x; Bs[lkv + 1][lrow] = b4.y;
        Bs[lkv + 2][lrow] = b4.z; Bs[lkv + 3][lrow] = b4.w;
        __syncthreads();

        #pragma unroll
        for (int k = 0; k < BK; k++) {
            __align__(16) float ra[8];
            __align__(16) unsigned long long rb[4];
            *(float4*)&ra[0] = *(const float4*)&As[k][ty * 8];
            *(float4*)&ra[4] = *(const float4*)&As[k][ty * 8 + 4];
            *(float4*)&rb[0] = *(const float4*)&Bs[k][tx * 8];      // cols 0..3
            *(float4*)&rb[2] = *(const float4*)&Bs[k][tx * 8 + 4];  // cols 4..7
            #pragma unroll
            for (int i = 0; i < 8; i++) {
                unsigned long long aa;
                asm("mov.b64 %0, {%1, %1};" : "=l"(aa) : "f"(ra[i]));
                #pragma unroll
                for (int j = 0; j < 4; j++)
                    asm("fma.rn.f32x2 %0, %1, %2, %0;"
                        : "+l"(acc[i][j]) : "l"(aa), "l"(rb[j]));
            }
        }
        __syncthreads();
    }

    float* Cb = C + (size_t)(blockIdx.y * BM + ty * 8) * N + blockIdx.x * BN + tx * 8;
    #pragma unroll
    for (int i = 0; i < 8; i++) {
        __align__(16) float o[8];
        #pragma unroll
        for (int j = 0; j < 4; j++) {
            float2 v = *(float2*)&acc[i][j];
            o[2 * j]     = v.x * alpha;
            o[2 * j + 1] = v.y * alpha;
        }
        *(float4*)(Cb + (size_t)i * N)     = *(float4*)&o[0];
        *(float4*)(Cb + (size_t)i * N + 4) = *(float4*)&o[4];
    }
}

// ---------------- 3) per-head L2 normalization (in place) --------------------
// one 64-thread block per (row, head) segment of HD=256 floats
__global__ void l2norm_heads(float* __restrict__ x)
{
    const int seg = blockIdx.x;
    const int tid = threadIdx.x;
    float4* p = (float4*)(x + (size_t)seg * HDm);
    float4 v = p[tid];
    float ss = v.x * v.x + v.y * v.y + v.z * v.z + v.w * v.w;
    #pragma unroll
    for (int o = 16; o > 0; o >>= 1) ss += __shfl_xor_sync(0xffffffffu, ss, o);
    __shared__ float sh[2];
    if ((tid & 31) == 0) sh[tid >> 5] = ss;
    __syncthreads();
    const float inv = 1.0f / fmaxf(sqrtf(sh[0] + sh[1]), 1e-12f);
    v.x *= inv; v.y *= inv; v.z *= inv; v.w *= inv;
    p[tid] = v;
}

// ---------------- 4) top-16 + softmax weights --------------------------------
// one block per row; iterative argmax over 2048 scores in shared
__global__ void topk_kernel(const float* __restrict__ S)
{
    const int row = blockIdx.x;
    const int tid = threadIdx.x;
    __shared__ float s[NC];            // 8 KB
    __shared__ float bv[256];
    __shared__ int   bi[256];
    __shared__ float topv[TOPK];
    __shared__ int   topi[TOPK];

    const float4* src = (const float4*)(S + (size_t)row * NC);
    ((float4*)s)[tid]       = src[tid];
    ((float4*)s)[tid + 256] = src[tid + 256];
    __syncthreads();

    for (int it = 0; it < TOPK; it++) {
        float best = -FLT_MAX; int bidx = 0x7fffffff;
        #pragma unroll
        for (int j = 0; j < 8; j++) {
            const int idx = tid * 8 + j;
            const float v = s[idx];
            if (v > best) { best = v; bidx = idx; }
        }
        bv[tid] = best; bi[tid] = bidx;
        __syncthreads();
        for (int off = 128; off > 0; off >>= 1) {
            if (tid < off) {
                const float v2 = bv[tid + off]; const int i2 = bi[tid + off];
                if (v2 > bv[tid] || (v2 == bv[tid] && i2 < bi[tid])) {
                    bv[tid] = v2; bi[tid] = i2;
                }
            }
            __syncthreads();
        }
        if (tid == 0) { topv[it] = bv[0]; topi[it] = bi[0]; s[bi[0]] = -FLT_MAX; }
        __syncthreads();
    }

    if (tid == 0) {
        float m = -FLT_MAX;
        #pragma unroll
        for (int i = 0; i < TOPK; i++) m = fmaxf(m, topv[i]);
        float e[TOPK]; float sum = 0.f;
        #pragma unroll
        for (int i = 0; i < TOPK; i++) { e[i] = expf(topv[i] - m); sum += e[i]; }
        const float invsum = 1.0f / sum;
        #pragma unroll
        for (int i = 0; i < TOPK; i++) {
            g_topw[row * TOPK + i] = e[i] * invsum;
            g_topi[row * TOPK + i] = topi[i];
        }
    }
}

// ---------------- 5) weighted blend of top-k prototypes ----------------------
__global__ void blend_kernel()
{
    const int row = blockIdx.x;
    const int tid = threadIdx.x;
    __shared__ float w[TOPK];
    __shared__ int   idx[TOPK];
    if (tid < TOPK) { w[tid] = g_topw[row * TOPK + tid]; idx[tid] = g_topi[row * TOPK + tid]; }
    __syncthreads();
    float4 acc = make_float4(0.f, 0.f, 0.f, 0.f);
    #pragma unroll
    for (int k = 0; k < TOPK; k++) {
        const float4* p = (const float4*)(g_protos + (size_t)idx[k] * Dm);
        const float4 v = p[tid];
        const float wk = w[k];
        acc.x += wk * v.x; acc.y += wk * v.y;
        acc.z += wk * v.z; acc.w += wk * v.w;
    }
    ((float4*)(g_retr + (size_t)row * Dm))[tid] = acc;
}

// ---------------- launcher ---------------------------------------------------
extern "C" void kernel_launch(void* const* d_in, const int* in_sizes, int n_in,
                              void* d_out, int out_size)
{
    const float* h      = (const float*)d_in[0];
    const float* protos = (const float*)d_in[1];
    const int*   ev     = (const int*)  d_in[2];
    const float* W_QR   = (const float*)d_in[3];
    const float* W_KR   = (const float*)d_in[4];
    const float* W_out  = (const float*)d_in[5];
    float* out = (float*)d_out;

    void *pp, *pq, *pk, *ps, *pr;
    cudaGetSymbolAddress(&pp, g_protos);
    cudaGetSymbolAddress(&pq, g_qr);
    cudaGetSymbolAddress(&pk, g_kr);
    cudaGetSymbolAddress(&ps, g_scores);
    cudaGetSymbolAddress(&pr, g_retr);
    float* gp = (float*)pp;
    float* gq = (float*)pq;
    float* gk = (float*)pk;
    float* gs = (float*)ps;
    float* gr = (float*)pr;

    // 1) compress prototypes (P=131072 -> 2048, l2-normalized)
    compress_kernel<<<NC, 256>>>(protos, ev);
    // 2) router projections
    sgemm_nt<<<dim3(Dm / 128, Bm / 128), 256>>>(h,  W_QR, gq, Bm, Dm, Dm, 1.0f);
    sgemm_nt<<<dim3(Dm / 128, NC / 128), 256>>>(gp, W_KR, gk, NC, Dm, Dm, 1.0f);
    // 3) per-head normalization (in place)
    l2norm_heads<<<Bm * Hh, 64>>>(gq);
    l2norm_heads<<<NC * Hh, 64>>>(gk);
    // 4) routing scores (mean over heads / temp folded into alpha = 2.5)
    sgemm_nt<<<dim3(NC / 128, Bm / 128), 256>>>(gq, gk, gs, Bm, NC, Dm, ALPHA_SCORES);
    // 5) top-16 + softmax
    topk_kernel<<<Bm, 256>>>(gs);
    // 6) blend
    blend_kernel<<<Bm, 256>>>();
    // 7) output projection
    sgemm_nt<<<dim3(Dm / 128, Bm / 128), 256>>>(gr, W_out, out, Bm, Dm, Dm, 1.0f);
}

// round 3
// speedup vs baseline: 1.0326x; 1.0326x over previous
#include <cuda_runtime.h>
#include <math.h>
#include <float.h>
#include <stdint.h>

// Problem constants
#define Dm    1024
#define Pfull 131072
#define Bm    4096
#define Hh    4
#define HDm   256
#define TOPK  16
#define CHUNK 64
#define NC    (Pfull / CHUNK)   // 2048 compressed prototypes
#define ALPHA_SCORES 2.5f       // 1 / (H * TEMP) = 1 / 0.4

// ---------------- scratch (static device globals; no allocation) -------------
__device__ float g_protos[NC * Dm];     // 8 MB  compressed+normalized prototypes
__device__ float g_qr[Bm * Dm];         // 16 MB query router proj (normalized in place)
__device__ float g_kr[NC * Dm];         // 8 MB  key router proj (normalized in place)
__device__ float g_scores[Bm * NC];     // 32 MB routing scores
__device__ float g_topw[Bm * TOPK];
__device__ int   g_topi[Bm * TOPK];
__device__ float g_retr[Bm * Dm];       // 16 MB blended retrieval

// ---------------- 1) chunk compression + L2 norm -----------------------------
__global__ void compress_kernel(const float* __restrict__ protos,
                                const int* __restrict__ ev)
{
    const int c   = blockIdx.x;
    const int tid = threadIdx.x;
    __shared__ float w[CHUNK];
    __shared__ float red[256];

    if (tid < CHUNK) w[tid] = (float)ev[c * CHUNK + tid] + 1e-8f;
    __syncthreads();
    if (tid == 0) {
        float s = 0.f;
        #pragma unroll
        for (int r = 0; r < CHUNK; r++) s += w[r];
        red[0] = 1.0f / s;
    }
    __syncthreads();
    const float invs = red[0];
    if (tid < CHUNK) w[tid] *= invs;
    __syncthreads();

    float4 acc = make_float4(0.f, 0.f, 0.f, 0.f);
    const float4* base = (const float4*)(protos + (size_t)c * CHUNK * Dm);
    #pragma unroll 4
    for (int r = 0; r < CHUNK; r++) {
        const float wr = w[r];
        float4 p = base[r * (Dm / 4) + tid];
        acc.x += wr * p.x; acc.y += wr * p.y;
        acc.z += wr * p.z; acc.w += wr * p.w;
    }
    red[tid] = acc.x * acc.x + acc.y * acc.y + acc.z * acc.z + acc.w * acc.w;
    __syncthreads();
    for (int s = 128; s > 0; s >>= 1) {
        if (tid < s) red[tid] += red[tid + s];
        __syncthreads();
    }
    const float inv = 1.0f / fmaxf(sqrtf(red[0]), 1e-12f);
    acc.x *= inv; acc.y *= inv; acc.z *= inv; acc.w *= inv;
    ((float4*)(g_protos + (size_t)c * Dm))[tid] = acc;
}

// ---------------- 2) NT SGEMM: C[M,N] = alpha * A[M,K] @ B[N,K]^T ------------
// 128x128x16 tile, double-buffered smem, 256 threads, 8x8 micro, f32x2 FMAs.
// One __syncthreads per k-tile; next tile's global loads prefetched into regs.
__global__ __launch_bounds__(256, 2)
void sgemm_nt(const float* __restrict__ A, const float* __restrict__ Bmat,
              float* __restrict__ C, int M, int N, int K, float alpha)
{
    const int BK = 16;
    __shared__ float As[2][BK][128];
    __shared__ float Bs[2][BK][128];

    const int tid = threadIdx.x;
    const int r0  = tid >> 2;          // 0..63
    const int c4  = (tid & 3) * 4;     // 0,4,8,12

    const float* Ap0 = A    + (size_t)(blockIdx.y * 128 + r0)      * K + c4;
    const float* Ap1 = A    + (size_t)(blockIdx.y * 128 + 64 + r0) * K + c4;
    const float* Bp0 = Bmat + (size_t)(blockIdx.x * 128 + r0)      * K + c4;
    const float* Bp1 = Bmat + (size_t)(blockIdx.x * 128 + 64 + r0) * K + c4;

    const int tx = tid & 15;           // N micro-tile
    const int ty = tid >> 4;           // M micro-tile

    unsigned long long acc[8][4];
    #pragma unroll
    for (int i = 0; i < 8; i++)
        #pragma unroll
        for (int j = 0; j < 4; j++) acc[i][j] = 0ull;

    // prologue: load tile 0, stage to smem buffer 0
    float4 a0 = *(const float4*)Ap0;
    float4 a1 = *(const float4*)Ap1;
    float4 b0 = *(const float4*)Bp0;
    float4 b1 = *(const float4*)Bp1;
    As[0][c4 + 0][r0] = a0.x; As[0][c4 + 1][r0] = a0.y;
    As[0][c4 + 2][r0] = a0.z; As[0][c4 + 3][r0] = a0.w;
    As[0][c4 + 0][64 + r0] = a1.x; As[0][c4 + 1][64 + r0] = a1.y;
    As[0][c4 + 2][64 + r0] = a1.z; As[0][c4 + 3][64 + r0] = a1.w;
    Bs[0][c4 + 0][r0] = b0.x; Bs[0][c4 + 1][r0] = b0.y;
    Bs[0][c4 + 2][r0] = b0.z; Bs[0][c4 + 3][r0] = b0.w;
    Bs[0][c4 + 0][64 + r0] = b1.x; Bs[0][c4 + 1][64 + r0] = b1.y;
    Bs[0][c4 + 2][64 + r0] = b1.z; Bs[0][c4 + 3][64 + r0] = b1.w;
    __syncthreads();

    const int ktiles = K / BK;
    int buf = 0;
    for (int t = 0; t < ktiles; t++) {
        const bool more = (t + 1 < ktiles);
        if (more) {
            const int k0 = (t + 1) * BK;
            a0 = *(const float4*)(Ap0 + k0);
            a1 = *(const float4*)(Ap1 + k0);
            b0 = *(const float4*)(Bp0 + k0);
            b1 = *(const float4*)(Bp1 + k0);
        }

        #pragma unroll
        for (int k = 0; k < BK; k++) {
            __align__(16) float ra[8];
            __align__(16) unsigned long long rb[4];
            *(float4*)&ra[0] = *(const float4*)&As[buf][k][ty * 8];
            *(float4*)&ra[4] = *(const float4*)&As[buf][k][ty * 8 + 4];
            *(float4*)&rb[0] = *(const float4*)&Bs[buf][k][tx * 8];
            *(float4*)&rb[2] = *(const float4*)&Bs[buf][k][tx * 8 + 4];
            #pragma unroll
            for (int i = 0; i < 8; i++) {
                unsigned long long aa;
                asm("mov.b64 %0, {%1, %1};" : "=l"(aa) : "f"(ra[i]));
                #pragma unroll
                for (int j = 0; j < 4; j++)
                    asm("fma.rn.f32x2 %0, %1, %2, %0;"
                        : "+l"(acc[i][j]) : "l"(aa), "l"(rb[j]));
            }
        }

        if (more) {
            const int nxt = buf ^ 1;
            As[nxt][c4 + 0][r0] = a0.x; As[nxt][c4 + 1][r0] = a0.y;
            As[nxt][c4 + 2][r0] = a0.z; As[nxt][c4 + 3][r0] = a0.w;
            As[nxt][c4 + 0][64 + r0] = a1.x; As[nxt][c4 + 1][64 + r0] = a1.y;
            As[nxt][c4 + 2][64 + r0] = a1.z; As[nxt][c4 + 3][64 + r0] = a1.w;
            Bs[nxt][c4 + 0][r0] = b0.x; Bs[nxt][c4 + 1][r0] = b0.y;
            Bs[nxt][c4 + 2][r0] = b0.z; Bs[nxt][c4 + 3][r0] = b0.w;
            Bs[nxt][c4 + 0][64 + r0] = b1.x; Bs[nxt][c4 + 1][64 + r0] = b1.y;
            Bs[nxt][c4 + 2][64 + r0] = b1.z; Bs[nxt][c4 + 3][64 + r0] = b1.w;
            __syncthreads();
            buf = nxt;
        }
    }

    float* Cb = C + (size_t)(blockIdx.y * 128 + ty * 8) * N + blockIdx.x * 128 + tx * 8;
    #pragma unroll
    for (int i = 0; i < 8; i++) {
        __align__(16) float o[8];
        #pragma unroll
        for (int j = 0; j < 4; j++) {
            float2 v = *(float2*)&acc[i][j];
            o[2 * j]     = v.x * alpha;
            o[2 * j + 1] = v.y * alpha;
        }
        *(float4*)(Cb + (size_t)i * N)     = *(float4*)&o[0];
        *(float4*)(Cb + (size_t)i * N + 4) = *(float4*)&o[4];
    }
}

// ---------------- 3) per-head L2 norm, one block per full row ----------------
// 256 threads handle 1024 floats (4 heads x 256); head = tid>>6.
__global__ void l2norm_rows(float* __restrict__ x)
{
    const int row = blockIdx.x;
    const int tid = threadIdx.x;
    float4* p = (float4*)(x + (size_t)row * Dm);
    float4 v = p[tid];
    float ss = v.x * v.x + v.y * v.y + v.z * v.z + v.w * v.w;
    #pragma unroll
    for (int o = 16; o > 0; o >>= 1) ss += __shfl_xor_sync(0xffffffffu, ss, o);
    __shared__ float ws[8];
    if ((tid & 31) == 0) ws[tid >> 5] = ss;
    __syncthreads();
    const int head2 = (tid >> 6) * 2;
    const float tot = ws[head2] + ws[head2 + 1];
    const float inv = 1.0f / fmaxf(sqrtf(tot), 1e-12f);
    v.x *= inv; v.y *= inv; v.z *= inv; v.w *= inv;
    p[tid] = v;
}

// ---------------- 4) top-16 + softmax (incremental argmax) -------------------
// Local per-thread maxima computed once; after each extraction only the owner
// thread rescans its 8 elements. Global reduction by warp 0 over 256 locals.
__global__ void topk_kernel(const float* __restrict__ S)
{
    const int row = blockIdx.x;
    const int tid = threadIdx.x;
    __shared__ float s[NC];            // 8 KB
    __shared__ float bv[256];
    __shared__ int   bi[256];
    __shared__ float topv[TOPK];
    __shared__ int   topi[TOPK];
    __shared__ int   owner;

    const float4* src = (const float4*)(S + (size_t)row * NC);
    ((float4*)s)[tid]       = src[tid];
    ((float4*)s)[tid + 256] = src[tid + 256];
    __syncthreads();

    // per-thread local argmax over 8 elements
    {
        float best = -FLT_MAX; int bidx = 0x7fffffff;
        #pragma unroll
        for (int j = 0; j < 8; j++) {
            const int idx = tid * 8 + j;
            const float v = s[idx];
            if (v > best) { best = v; bidx = idx; }
        }
        bv[tid] = best; bi[tid] = bidx;
    }
    __syncthreads();

    for (int it = 0; it < TOPK; it++) {
        if (tid < 32) {
            float best = -FLT_MAX; int bidx = 0x7fffffff;
            #pragma unroll
            for (int j = 0; j < 8; j++) {
                const float v = bv[tid * 8 + j];
                const int   i = bi[tid * 8 + j];
                if (v > best || (v == best && i < bidx)) { best = v; bidx = i; }
            }
            #pragma unroll
            for (int off = 16; off > 0; off >>= 1) {
                const float v2 = __shfl_xor_sync(0xffffffffu, best, off);
                const int   i2 = __shfl_xor_sync(0xffffffffu, bidx, off);
                if (v2 > best || (v2 == best && i2 < bidx)) { best = v2; bidx = i2; }
            }
            if (tid == 0) {
                topv[it] = best; topi[it] = bidx;
                s[bidx] = -FLT_MAX;
                owner = bidx >> 3;
            }
        }
        __syncthreads();
        if (tid == owner) {
            float best = -FLT_MAX; int bidx = 0x7fffffff;
            #pragma unroll
            for (int j = 0; j < 8; j++) {
                const int idx = tid * 8 + j;
                const float v = s[idx];
                if (v > best) { best = v; bidx = idx; }
            }
            bv[tid] = best; bi[tid] = bidx;
        }
        __syncthreads();
    }

    if (tid == 0) {
        float m = -FLT_MAX;
        #pragma unroll
        for (int i = 0; i < TOPK; i++) m = fmaxf(m, topv[i]);
        float e[TOPK]; float sum = 0.f;
        #pragma unroll
        for (int i = 0; i < TOPK; i++) { e[i] = expf(topv[i] - m); sum += e[i]; }
        const float invsum = 1.0f / sum;
        #pragma unroll
        for (int i = 0; i < TOPK; i++) {
            g_topw[row * TOPK + i] = e[i] * invsum;
            g_topi[row * TOPK + i] = topi[i];
        }
    }
}

// ---------------- 5) weighted blend of top-k prototypes ----------------------
__global__ void blend_kernel()
{
    const int row = blockIdx.x;
    const int tid = threadIdx.x;
    __shared__ float w[TOPK];
    __shared__ int   idx[TOPK];
    if (tid < TOPK) { w[tid] = g_topw[row * TOPK + tid]; idx[tid] = g_topi[row * TOPK + tid]; }
    __syncthreads();
    float4 acc = make_float4(0.f, 0.f, 0.f, 0.f);
    #pragma unroll
    for (int k = 0; k < TOPK; k++) {
        const float4* p = (const float4*)(g_protos + (size_t)idx[k] * Dm);
        const float4 v = p[tid];
        const float wk = w[k];
        acc.x += wk * v.x; acc.y += wk * v.y;
        acc.z += wk * v.z; acc.w += wk * v.w;
    }
    ((float4*)(g_retr + (size_t)row * Dm))[tid] = acc;
}

// ---------------- launcher ---------------------------------------------------
extern "C" void kernel_launch(void* const* d_in, const int* in_sizes, int n_in,
                              void* d_out, int out_size)
{
    const float* h      = (const float*)d_in[0];
    const float* protos = (const float*)d_in[1];
    const int*   ev     = (const int*)  d_in[2];
    const float* W_QR   = (const float*)d_in[3];
    const float* W_KR   = (const float*)d_in[4];
    const float* W_out  = (const float*)d_in[5];
    float* out = (float*)d_out;

    void *pp, *pq, *pk, *ps, *pr;
    cudaGetSymbolAddress(&pp, g_protos);
    cudaGetSymbolAddress(&pq, g_qr);
    cudaGetSymbolAddress(&pk, g_kr);
    cudaGetSymbolAddress(&ps, g_scores);
    cudaGetSymbolAddress(&pr, g_retr);
    float* gp = (float*)pp;
    float* gq = (float*)pq;
    float* gk = (float*)pk;
    float* gs = (float*)ps;
    float* gr = (float*)pr;

    // 1) compress prototypes (P=131072 -> 2048, l2-normalized)
    compress_kernel<<<NC, 256>>>(protos, ev);
    // 2) router projections
    sgemm_nt<<<dim3(Dm / 128, Bm / 128), 256>>>(h,  W_QR, gq, Bm, Dm, Dm, 1.0f);
    sgemm_nt<<<dim3(Dm / 128, NC / 128), 256>>>(gp, W_KR, gk, NC, Dm, Dm, 1.0f);
    // 3) per-head normalization (in place)
    l2norm_rows<<<Bm, 256>>>(gq);
    l2norm_rows<<<NC, 256>>>(gk);
    // 4) routing scores (mean over heads / temp folded into alpha = 2.5)
    sgemm_nt<<<dim3(NC / 128, Bm / 128), 256>>>(gq, gk, gs, Bm, NC, Dm, ALPHA_SCORES);
    // 5) top-16 + softmax
    topk_kernel<<<Bm, 256>>>(gs);
    // 6) blend
    blend_kernel<<<Bm, 256>>>();
    // 7) output projection
    sgemm_nt<<<dim3(Dm / 128, Bm / 128), 256>>>(gr, W_out, out, Bm, Dm, Dm, 1.0f);
}